// round 1
// baseline (speedup 1.0000x reference)
#include <cuda_runtime.h>
#include <cuda_bf16.h>

// Inputs (metadata order, matching reference signature):
//  d_in[0] charges             float32 [200000, 4]
//  d_in[1] cell                float32 [3, 3]        (unused)
//  d_in[2] positions           float32 [200000, 3]   (unused)
//  d_in[3] neighbor_indices    int32   [12800000, 2]
//  d_in[4] neighbor_distances  float32 [12800000]
//  d_out  potential            float32 [200000, 4]
//
// out = 0.5 * scatter_add over edges:
//   out[i] += charges[j] / d;  out[j] += charges[i] / d

__device__ __forceinline__ void red_add_v4(float4* p, float x, float y, float z, float w) {
    asm volatile("red.global.add.v4.f32 [%0], {%1, %2, %3, %4};"
                 :: "l"(p), "f"(x), "f"(y), "f"(z), "f"(w)
                 : "memory");
}

__global__ void __launch_bounds__(256)
edge_scatter_kernel(const float4* __restrict__ charges,
                    const int2*   __restrict__ nbr,
                    const float*  __restrict__ dist,
                    float4*       __restrict__ out,
                    int n_edges) {
    int e = blockIdx.x * blockDim.x + threadIdx.x;
    if (e >= n_edges) return;

    int2  ij  = __ldg(&nbr[e]);
    float d   = __ldg(&dist[e]);
    float inv = 0.5f / d;   // fold PREFACTOR*0.5

    float4 cj = __ldg(&charges[ij.y]);
    float4 ci = __ldg(&charges[ij.x]);

    // out[i] += charges[j] * inv
    red_add_v4(&out[ij.x], cj.x * inv, cj.y * inv, cj.z * inv, cj.w * inv);
    // out[j] += charges[i] * inv
    red_add_v4(&out[ij.y], ci.x * inv, ci.y * inv, ci.z * inv, ci.w * inv);
}

extern "C" void kernel_launch(void* const* d_in, const int* in_sizes, int n_in,
                              void* d_out, int out_size) {
    const float4* charges = (const float4*)d_in[0];
    const int2*   nbr     = (const int2*)d_in[3];
    const float*  dist    = (const float*)d_in[4];
    float4*       out     = (float4*)d_out;

    int n_edges = in_sizes[4];          // 12,800,000

    // d_out is poisoned to 0xAA — zero it (async, graph-capturable).
    cudaMemsetAsync(d_out, 0, (size_t)out_size * sizeof(float));

    const int TPB = 256;
    int blocks = (n_edges + TPB - 1) / TPB;
    edge_scatter_kernel<<<blocks, TPB>>>(charges, nbr, dist, out, n_edges);
}